// round 9
// baseline (speedup 1.0000x reference)
#include <cuda_runtime.h>
#include <math.h>

#define BATCH   32
#define TT      256
#define EE      256
#define CC      256
#define SLEN    192                 // 256 - 64
#define NROWS   (BATCH * SLEN)      // 6144
#define NSTEPS  12
#define RB      32                  // rows per block
#define CT      128                 // columns per tile
#define KC      16                  // K-chunk (phase 2)
#define NHALF   2
#define CPB     (NROWS / NHALF)     // 3072 cols swept per block
#define OFFSET  40.0f
#define TOTAL_COUNT 71616.0
#define PSTR    32                  // Pst row stride (floats)
#define SSTR    132                 // stage row stride (floats)

// Packed f32x2 helpers (Blackwell)
#define FMA_F32X2(d, a, b) \
    asm("fma.rn.f32x2 %0, %1, %2, %0;" : "+l"(d) : "l"(a), "l"(b))
#define PACK_DUP(d, x) \
    asm("mov.b64 %0, {%1, %1};" : "=l"(d) : "r"(__float_as_uint(x)))
#define UNPACK2(lo, hi, p) \
    asm("mov.b64 {%0, %1}, %2;" : "=f"(lo), "=f"(hi) : "l"(p))

// Cross-kernel scratch
__device__ float g_CtxT[CC * NROWS];               // ctx, K-major (6 MB)
__device__ float g_part[NROWS * 13 * NHALF];       // per row: [head, tail(v=181..191)] x half
__device__ float g_pos [NROWS * NSTEPS];           // positives

// ---------------------------------------------------------------------------
// Prep: gather + transpose contexts -> g_CtxT[k][c] = ctx[j][63+v][k]
// ---------------------------------------------------------------------------
__global__ void __launch_bounds__(256) prep_ctxT(const float* __restrict__ ctx) {
    __shared__ float sm[32 * 257];
    int tid = threadIdx.x;
    int c0  = blockIdx.x * 32;

    for (int idx = tid; idx < 32 * 256; idx += 256) {
        int i = idx >> 8, k = idx & 255;
        int c = c0 + i;
        int j = c / SLEN, v = c - j * SLEN;
        sm[i * 257 + k] = ctx[((j * TT) + 63 + v) * CC + k];
    }
    __syncthreads();
    for (int idx = tid; idx < 32 * 256; idx += 256) {
        int k = idx >> 5, i = idx & 31;
        g_CtxT[k * NROWS + c0 + i] = sm[i * 257 + k];
    }
}

// ---------------------------------------------------------------------------
// Fused kernel. grid = (2 halves, 192 row-groups), block = 256.
// Static smem: 32768 + 8448 + 1408 = 42624 B (< 48 KB)
// ---------------------------------------------------------------------------
__global__ void __launch_bounds__(256, 2) fused(const float* __restrict__ emb,
                                                const float* __restrict__ ctx,
                                                const float* __restrict__ W) {
    __shared__ float Pst[256 * PSTR];     // K-major P stripe, 32 KB
    __shared__ float stage[KC * SSTR];    // 8.25 KB (reused for emb chunks)
    __shared__ float sTail[RB * 11];      // per-row tail sums

    int tid  = threadIdx.x;
    int tx   = tid & 31;                  // lane -> cols tx*4..tx*4+3
    int ty   = tid >> 5;                  // warp -> rows ty*4..ty*4+3
    int half = blockIdx.x;
    int r0   = blockIdx.y * RB;
    int b    = r0 / SLEN;
    int u0   = r0 - b * SLEN;

    // ---- Phase 1: P stripe (32 rows x 256 cols); thread owns channel tid ----
    {
        float acc[RB];
        #pragma unroll
        for (int i = 0; i < RB; ++i) acc[i] = 0.f;

        for (int e0 = 0; e0 < EE; e0 += 64) {
            __syncthreads();
            for (int idx = tid; idx < RB * 64; idx += 256) {
                int i = idx >> 6, e = idx & 63;
                stage[i * 66 + e] = emb[((b * TT) + 64 + u0 + i) * EE + e0 + e];
            }
            __syncthreads();
            #pragma unroll 4
            for (int e = 0; e < 64; ++e) {
                float w = W[(e0 + e) * CC + tid];
                #pragma unroll
                for (int i = 0; i < RB; ++i) acc[i] += stage[i * 66 + e] * w;
            }
        }
        #pragma unroll
        for (int i = 0; i < RB; ++i) Pst[tid * PSTR + i] = acc[i];   // K-major
    }
    for (int idx = tid; idx < RB * 11; idx += 256) sTail[idx] = 0.f;
    __syncthreads();

    // ---- Phase 2: sweep this half's 3072 columns (packed f32x2 FMA) ----
    float head[4] = {0.f, 0.f, 0.f, 0.f};   // sum over v < 181 only
    int c0base = half * CPB;

    for (int t = 0; t < CPB / CT; ++t) {             // 24 tiles of 128 cols
        int c0 = c0base + t * CT;

        unsigned long long acc[4][2];                // 4 rows x 2 col-pairs
        #pragma unroll
        for (int i = 0; i < 4; ++i) { acc[i][0] = 0ULL; acc[i][1] = 0ULL; }

        for (int k0 = 0; k0 < CC; k0 += KC) {
            __syncthreads();
            #pragma unroll
            for (int q = 0; q < 2; ++q) {            // 512 float4 / 256 threads
                int flat = tid + q * 256;
                int k    = flat >> 5;
                int col  = (flat & 31) * 4;
                float4 v = *(const float4*)&g_CtxT[(size_t)(k0 + k) * NROWS + c0 + col];
                *(float4*)&stage[k * SSTR + col] = v;
            }
            __syncthreads();

            #pragma unroll
            for (int k = 0; k < KC; ++k) {
                float4 a = *(const float4*)&Pst[(k0 + k) * PSTR + ty * 4]; // broadcast
                ulonglong2 bp = *(const ulonglong2*)&stage[k * SSTR + tx * 4]; // 2 packed pairs
                unsigned long long ax;
                PACK_DUP(ax, a.x);
                FMA_F32X2(acc[0][0], ax, bp.x); FMA_F32X2(acc[0][1], ax, bp.y);
                PACK_DUP(ax, a.y);
                FMA_F32X2(acc[1][0], ax, bp.x); FMA_F32X2(acc[1][1], ax, bp.y);
                PACK_DUP(ax, a.z);
                FMA_F32X2(acc[2][0], ax, bp.x); FMA_F32X2(acc[2][1], ax, bp.y);
                PACK_DUP(ax, a.w);
                FMA_F32X2(acc[3][0], ax, bp.x); FMA_F32X2(acc[3][1], ax, bp.y);
            }
        }

        // epilogue: exp -> head (v<181) or tail atomics (v>=181); addition only
        #pragma unroll
        for (int i = 0; i < 4; ++i) {
            float tloc = 0.f;
            #pragma unroll
            for (int p = 0; p < 2; ++p) {
                float s0, s1;
                UNPACK2(s0, s1, acc[i][p]);
                int cBase = c0 + tx * 4 + p * 2;
                float e0v = __expf(s0 - OFFSET);
                float e1v = __expf(s1 - OFFSET);
                int v0 = cBase % SLEN;
                int v1 = (cBase + 1) % SLEN;
                if (v0 < 181) tloc += e0v;
                else atomicAdd(&sTail[(ty * 4 + i) * 11 + (v0 - 181)], e0v);
                if (v1 < 181) tloc += e1v;
                else atomicAdd(&sTail[(ty * 4 + i) * 11 + (v1 - 181)], e1v);
            }
            head[i] += tloc;     // two-level accumulation trims sequential error
        }
    }

    // ---- reduce heads across lanes; write per-row data ----
    #pragma unroll
    for (int i = 0; i < 4; ++i) {
        float v = head[i];
        #pragma unroll
        for (int off = 16; off; off >>= 1)
            v += __shfl_down_sync(0xffffffffu, v, off);
        if (tx == 0) {
            int r = r0 + ty * 4 + i;
            g_part[(r * 13 + 0) * NHALF + half] = v;
        }
    }
    __syncthreads();
    if (tid < RB) {
        int r = r0 + tid;
        for (int t = 0; t < 11; ++t)
            g_part[(r * 13 + 1 + t) * NHALF + half] = sTail[tid * 11 + t];
    }

    // ---- positives (half 0, warp 0) ----
    if (half == 0 && tid < 32) {
        int i = tid;
        int u = u0 + i;
        int r = r0 + i;
        int smax = (u < 11) ? u : 11;
        for (int s = 0; s <= smax; ++s) {
            const float* crow = ctx + ((b * TT) + 63 + (u - s)) * CC;
            float pos = 0.f;
            #pragma unroll 4
            for (int k = 0; k < CC; ++k) pos += Pst[k * PSTR + i] * crow[k];
            g_pos[r * NSTEPS + s] = pos;
        }
    }
}

// ---------------------------------------------------------------------------
// Finalize: S_s = head + prefix-sum of tails (ADDITION ONLY), reduce.
// ---------------------------------------------------------------------------
__global__ void __launch_bounds__(1024) finalize(float* __restrict__ out, int out_size) {
    __shared__ double sred[1024];
    __shared__ float slogN[NSTEPS];
    int tid = threadIdx.x;
    if (tid < NSTEPS) slogN[tid] = logf((float)(BATCH * (SLEN - tid)));
    __syncthreads();

    double s = 0.0;
    for (int r = tid; r < NROWS; r += 1024) {
        float hd = g_part[(r * 13) * NHALF] + g_part[(r * 13) * NHALF + 1];
        // pref[m] = sum of first m tails (tail t = columns v = 181+t)
        float pref[12];
        pref[0] = 0.f;
        #pragma unroll
        for (int t = 0; t < 11; ++t)
            pref[t + 1] = pref[t]
                        + g_part[(r * 13 + 1 + t) * NHALF]
                        + g_part[(r * 13 + 1 + t) * NHALF + 1];
        int u = r % SLEN;
        int smax = (u < 11) ? u : 11;
        for (int st = 0; st <= smax; ++st) {
            float S = hd + pref[11 - st];       // includes tails t <= 10 - st
            float lse = OFFSET + logf(fmaxf(S, 1e-35f)) - slogN[st];
            s += (double)(g_pos[r * NSTEPS + st] - lse);
        }
    }
    sred[tid] = s;
    __syncthreads();
    for (int k = 512; k > 0; k >>= 1) {
        if (tid < k) sred[tid] += sred[tid + k];
        __syncthreads();
    }
    float val = (float)(-sred[0] / TOTAL_COUNT);
    for (int i = tid; i < out_size; i += 1024) out[i] = val;
}

// ---------------------------------------------------------------------------
extern "C" void kernel_launch(void* const* d_in, const int* in_sizes, int n_in,
                              void* d_out, int out_size) {
    int wIdx = -1;
    for (int i = 0; i < n_in; ++i)
        if (in_sizes[i] == EE * CC) { wIdx = i; break; }
    if (wIdx < 0) wIdx = 2;
    int others[2]; int no = 0;
    for (int i = 0; i < n_in && no < 2; ++i)
        if (i != wIdx) others[no++] = i;

    const float* embeddings = (const float*)d_in[others[0]];  // (32,256,256)
    const float* contexts   = (const float*)d_in[others[1]];  // (32,256,256)
    const float* W          = (const float*)d_in[wIdx];       // (256,256)
    float* out = (float*)d_out;

    prep_ctxT<<<NROWS / 32, 256>>>(contexts);
    fused<<<dim3(NHALF, NROWS / RB), 256>>>(embeddings, contexts, W);
    finalize<<<1, 1024>>>(out, out_size);
}

// round 11
// speedup vs baseline: 3.3912x; 3.3912x over previous
#include <cuda_runtime.h>
#include <cuda_bf16.h>
#include <math.h>
#include <cstdint>

#define BATCH   32
#define TT      256
#define EE      256
#define CC      256
#define SLEN    192
#define NROWS   (BATCH * SLEN)      // 6144
#define NSTEPS  12
#define K3      768                 // stacked K: [hi|hi|lo] . [hi|lo|hi]
#define NCHUNK  12                  // K3 / 64
#define OFFSET  40.0f
#define TOTAL_COUNT 71616.0
#define SSTRIDE 80                  // smem row stride in bf16 (160B, 16B-aligned)

// ---------------- scratch ----------------
__device__ float          g_P[NROWS * CC];           // fp32 projections (6 MB)
__device__ __nv_bfloat16  g_A3[(size_t)NROWS * K3];  // 9 MB
__device__ __nv_bfloat16  g_B3[(size_t)NROWS * K3];  // 9 MB
__device__ float          g_head[NROWS];
__device__ float          g_tail[NROWS * 11];
__device__ float          g_pos [NROWS * NSTEPS];

// ---------------------------------------------------------------------------
// 1) build_P: P = emb_slice @ W (fp32). grid 192, block 256, 32 rows/blk.
// ---------------------------------------------------------------------------
__global__ void __launch_bounds__(256) build_P(const float* __restrict__ emb,
                                               const float* __restrict__ W) {
    __shared__ float stage[32 * 66];
    int tid = threadIdx.x;
    int r0  = blockIdx.x * 32;
    int b   = r0 / SLEN;
    int u0  = r0 - b * SLEN;

    float acc[32];
    #pragma unroll
    for (int i = 0; i < 32; ++i) acc[i] = 0.f;

    for (int e0 = 0; e0 < EE; e0 += 64) {
        __syncthreads();
        for (int idx = tid; idx < 32 * 64; idx += 256) {
            int i = idx >> 6, e = idx & 63;
            stage[i * 66 + e] = emb[((b * TT) + 64 + u0 + i) * EE + e0 + e];
        }
        __syncthreads();
        #pragma unroll 4
        for (int e = 0; e < 64; ++e) {
            float w = W[(e0 + e) * CC + tid];
            #pragma unroll
            for (int i = 0; i < 32; ++i) acc[i] += stage[i * 66 + e] * w;
        }
    }
    #pragma unroll
    for (int i = 0; i < 32; ++i) g_P[(r0 + i) * CC + tid] = acc[i];
}

// ---------------------------------------------------------------------------
// 2) split_A: A3 row = [hi(P) | hi(P) | lo(P)]; also zeroes head/tail.
// ---------------------------------------------------------------------------
__global__ void __launch_bounds__(256) split_A() {
    int r = blockIdx.x, tid = threadIdx.x;
    float x = g_P[r * CC + tid];
    __nv_bfloat16 hi = __float2bfloat16(x);
    __nv_bfloat16 lo = __float2bfloat16(x - __bfloat162float(hi));
    size_t base = (size_t)r * K3;
    g_A3[base + tid]       = hi;
    g_A3[base + 256 + tid] = hi;
    g_A3[base + 512 + tid] = lo;
    if (tid == 0) g_head[r] = 0.f;
    if (tid < 11) g_tail[r * 11 + tid] = 0.f;
}

// ---------------------------------------------------------------------------
// 3) split_B: B3 row = [hi(C) | lo(C) | hi(C)] from gathered ctx.
// ---------------------------------------------------------------------------
__global__ void __launch_bounds__(256) split_B(const float* __restrict__ ctx) {
    int c = blockIdx.x, tid = threadIdx.x;
    int j = c / SLEN, v = c - j * SLEN;
    float x = ctx[((j * TT) + 63 + v) * CC + tid];
    __nv_bfloat16 hi = __float2bfloat16(x);
    __nv_bfloat16 lo = __float2bfloat16(x - __bfloat162float(hi));
    size_t base = (size_t)c * K3;
    g_B3[base + tid]       = hi;
    g_B3[base + 256 + tid] = lo;
    g_B3[base + 512 + tid] = hi;
}

// ---------------------------------------------------------------------------
// 4) positives: g_pos[r][s] = dot(P[r], ctx[b][63+u-s]) fp32. 1 warp/row.
// ---------------------------------------------------------------------------
__global__ void __launch_bounds__(256) positives(const float* __restrict__ ctx) {
    int tid = threadIdx.x, wid = tid >> 5, lane = tid & 31;
    int r = blockIdx.x * 8 + wid;
    int b = r / SLEN, u = r - b * SLEN;

    float p[8];
    #pragma unroll
    for (int i = 0; i < 8; ++i) p[i] = g_P[r * CC + lane + i * 32];

    int smax = (u < 11) ? u : 11;
    for (int s = 0; s <= smax; ++s) {
        const float* crow = ctx + ((b * TT) + 63 + (u - s)) * CC;
        float acc = 0.f;
        #pragma unroll
        for (int i = 0; i < 8; ++i) acc += p[i] * crow[lane + i * 32];
        #pragma unroll
        for (int off = 16; off; off >>= 1)
            acc += __shfl_down_sync(0xffffffffu, acc, off);
        if (lane == 0) g_pos[r * NSTEPS + s] = acc;
    }
}

// ---------------------------------------------------------------------------
// 5) gemm_mma: warp-level mma.sync bf16 GEMM (baseline PTX, works on sm_100).
//    128x128 tile/CTA, 8 warps (2 M x 4 N), each warp 64x32.
//    Epilogue: exp(x-40) -> head/tail. grid (48,48), block 256.
// ---------------------------------------------------------------------------
__device__ __forceinline__ void mma16816(float* d, const uint32_t* a, const uint32_t* b) {
    asm volatile(
        "mma.sync.aligned.m16n8k16.row.col.f32.bf16.bf16.f32 "
        "{%0,%1,%2,%3}, {%4,%5,%6,%7}, {%8,%9}, {%0,%1,%2,%3};"
        : "+f"(d[0]), "+f"(d[1]), "+f"(d[2]), "+f"(d[3])
        : "r"(a[0]), "r"(a[1]), "r"(a[2]), "r"(a[3]), "r"(b[0]), "r"(b[1]));
}

__global__ void __launch_bounds__(256) gemm_mma() {
    __shared__ __nv_bfloat16 sA[128 * SSTRIDE];   // 20.5 KB
    __shared__ __nv_bfloat16 sB[128 * SSTRIDE];   // 20.5 KB

    int tid  = threadIdx.x;
    int wid  = tid >> 5;
    int lane = tid & 31;
    int g    = lane >> 2;          // 0..7
    int tg   = lane & 3;           // 0..3
    int wM   = wid & 1;            // rows wM*64
    int wN   = wid >> 1;           // cols wN*32
    int row0 = blockIdx.y * 128;
    int col0 = blockIdx.x * 128;

    float d[4][4][4];              // [mi][ni][reg]
    #pragma unroll
    for (int mi = 0; mi < 4; ++mi)
        #pragma unroll
        for (int ni = 0; ni < 4; ++ni)
            #pragma unroll
            for (int q = 0; q < 4; ++q) d[mi][ni][q] = 0.f;

    for (int ch = 0; ch < NCHUNK; ++ch) {
        __syncthreads();
        #pragma unroll
        for (int i = 0; i < 4; ++i) {
            int idx = tid + i * 256;           // 0..1023
            int rr  = idx >> 3;                // 0..127
            int c8  = (idx & 7) * 8;           // bf16 offset within 64-wide chunk
            *(uint4*)&sA[rr * SSTRIDE + c8] =
                *(const uint4*)&g_A3[(size_t)(row0 + rr) * K3 + ch * 64 + c8];
            *(uint4*)&sB[rr * SSTRIDE + c8] =
                *(const uint4*)&g_B3[(size_t)(col0 + rr) * K3 + ch * 64 + c8];
        }
        __syncthreads();

        #pragma unroll
        for (int ks = 0; ks < 4; ++ks) {        // 4 k-steps of 16
            int kb = ks * 16;
            uint32_t bfr[4][2];
            #pragma unroll
            for (int ni = 0; ni < 4; ++ni) {
                const __nv_bfloat16* bp = &sB[(wN * 32 + ni * 8 + g) * SSTRIDE + kb + tg * 2];
                bfr[ni][0] = *(const uint32_t*)bp;
                bfr[ni][1] = *(const uint32_t*)(bp + 8);
            }
            #pragma unroll
            for (int mi = 0; mi < 4; ++mi) {
                const __nv_bfloat16* ap = &sA[(wM * 64 + mi * 16 + g) * SSTRIDE + kb + tg * 2];
                uint32_t afr[4];
                afr[0] = *(const uint32_t*)ap;                 // (g,   k0-1)
                afr[1] = *(const uint32_t*)(ap + 8 * SSTRIDE); // (g+8, k0-1)
                afr[2] = *(const uint32_t*)(ap + 8);           // (g,   k8-9)
                afr[3] = *(const uint32_t*)(ap + 8 * SSTRIDE + 8);
                #pragma unroll
                for (int ni = 0; ni < 4; ++ni)
                    mma16816(d[mi][ni], afr, bfr[ni]);
            }
        }
    }

    // ---- epilogue: exp + head/tail ----
    float headLo[4] = {0, 0, 0, 0}, headHi[4] = {0, 0, 0, 0};
    #pragma unroll
    for (int mi = 0; mi < 4; ++mi) {
        int rLo = row0 + wM * 64 + mi * 16 + g;
        int rHi = rLo + 8;
        #pragma unroll
        for (int ni = 0; ni < 4; ++ni) {
            int c0c = col0 + wN * 32 + ni * 8 + tg * 2;
            #pragma unroll
            for (int q = 0; q < 2; ++q) {       // q: column pair (c0c + q)
                int cc = c0c + q;
                int v  = cc % SLEN;
                float eLo = __expf(d[mi][ni][q]     - OFFSET);
                float eHi = __expf(d[mi][ni][q + 2] - OFFSET);
                if (v < 181) { headLo[mi] += eLo; headHi[mi] += eHi; }
                else {
                    atomicAdd(&g_tail[rLo * 11 + (v - 181)], eLo);
                    atomicAdd(&g_tail[rHi * 11 + (v - 181)], eHi);
                }
            }
        }
    }
    // quad-reduce over tg (lanes g*4 .. g*4+3 share rows)
    #pragma unroll
    for (int mi = 0; mi < 4; ++mi) {
        float lo = headLo[mi], hi = headHi[mi];
        lo += __shfl_down_sync(0xffffffffu, lo, 2, 4);
        lo += __shfl_down_sync(0xffffffffu, lo, 1, 4);
        hi += __shfl_down_sync(0xffffffffu, hi, 2, 4);
        hi += __shfl_down_sync(0xffffffffu, hi, 1, 4);
        if (tg == 0) {
            int rLo = row0 + wM * 64 + mi * 16 + g;
            atomicAdd(&g_head[rLo],     lo);
            atomicAdd(&g_head[rLo + 8], hi);
        }
    }
}

// ---------------------------------------------------------------------------
// 6) finalize: S_s = head + prefix(tails) (addition only). 1024 threads.
// ---------------------------------------------------------------------------
__global__ void __launch_bounds__(1024) finalize(float* __restrict__ out, int out_size) {
    __shared__ double sred[1024];
    __shared__ float slogN[NSTEPS];
    int tid = threadIdx.x;
    if (tid < NSTEPS) slogN[tid] = logf((float)(BATCH * (SLEN - tid)));
    __syncthreads();

    double s = 0.0;
    for (int r = tid; r < NROWS; r += 1024) {
        float hd = g_head[r];
        float pref[12];
        pref[0] = 0.f;
        #pragma unroll
        for (int t = 0; t < 11; ++t) pref[t + 1] = pref[t] + g_tail[r * 11 + t];
        int u = r % SLEN;
        int smax = (u < 11) ? u : 11;
        for (int st = 0; st <= smax; ++st) {
            float S = hd + pref[11 - st];
            float lse = OFFSET + logf(fmaxf(S, 1e-35f)) - slogN[st];
            s += (double)(g_pos[r * NSTEPS + st] - lse);
        }
    }
    sred[tid] = s;
    __syncthreads();
    for (int k = 512; k > 0; k >>= 1) {
        if (tid < k) sred[tid] += sred[tid + k];
        __syncthreads();
    }
    float val = (float)(-sred[0] / TOTAL_COUNT);
    for (int i = tid; i < out_size; i += 1024) out[i] = val;
}

// ---------------------------------------------------------------------------
extern "C" void kernel_launch(void* const* d_in, const int* in_sizes, int n_in,
                              void* d_out, int out_size) {
    int wIdx = -1;
    for (int i = 0; i < n_in; ++i)
        if (in_sizes[i] == EE * CC) { wIdx = i; break; }
    if (wIdx < 0) wIdx = 2;
    int others[2]; int no = 0;
    for (int i = 0; i < n_in && no < 2; ++i)
        if (i != wIdx) others[no++] = i;

    const float* embeddings = (const float*)d_in[others[0]];  // (32,256,256)
    const float* contexts   = (const float*)d_in[others[1]];  // (32,256,256)
    const float* W          = (const float*)d_in[wIdx];       // (256,256)
    float* out = (float*)d_out;

    build_P<<<NROWS / 32, 256>>>(embeddings, W);
    split_A<<<NROWS, 256>>>();
    split_B<<<NROWS, 256>>>(contexts);
    positives<<<NROWS / 8, 256>>>(contexts);
    gemm_mma<<<dim3(48, 48), 256>>>();
    finalize<<<1, 1024>>>(out, out_size);
}

// round 12
// speedup vs baseline: 3.7478x; 1.1052x over previous
#include <cuda_runtime.h>
#include <cuda_bf16.h>
#include <math.h>
#include <cstdint>

#define BATCH   32
#define TT      256
#define EE      256
#define CC      256
#define SLEN    192
#define NROWS   (BATCH * SLEN)      // 6144
#define NSTEPS  12
#define K3      768                 // stacked K: [hi|hi|lo] . [hi|lo|hi]
#define KCH     32                  // k per chunk (async pipeline)
#define NCH     (K3 / KCH)          // 24
#define OFFSET  40.0f
#define TOTAL_COUNT 71616.0
#define SST     40                  // smem row stride (bf16): 80B, 5x16B -> ldmatrix conflict-free

// ---------------- scratch ----------------
__device__ float          g_P[NROWS * CC];           // fp32 projections (6 MB)
__device__ __nv_bfloat16  g_A3[(size_t)NROWS * K3];  // 9 MB
__device__ __nv_bfloat16  g_B3[(size_t)NROWS * K3];  // 9 MB
__device__ float          g_head[NROWS];
__device__ float          g_tail[NROWS * 11];
__device__ float          g_pos [NROWS * NSTEPS];

// ---------------- asm helpers ----------------
#define CP_ASYNC16(sa, gp) \
    asm volatile("cp.async.ca.shared.global [%0], [%1], 16;" :: "r"(sa), "l"(gp))
#define CP_COMMIT() asm volatile("cp.async.commit_group;" ::: "memory")
#define CP_WAIT(n)  asm volatile("cp.async.wait_group %0;" :: "n"(n) : "memory")
#define LDMX4(r0, r1, r2, r3, addr) \
    asm volatile("ldmatrix.sync.aligned.m8n8.x4.shared.b16 {%0,%1,%2,%3}, [%4];" \
                 : "=r"(r0), "=r"(r1), "=r"(r2), "=r"(r3) : "r"(addr))

__device__ __forceinline__ uint32_t smem_u32(const void* p) {
    return (uint32_t)__cvta_generic_to_shared(p);
}
__device__ __forceinline__ void mma16816(float* d, const uint32_t* a, const uint32_t* b) {
    asm volatile(
        "mma.sync.aligned.m16n8k16.row.col.f32.bf16.bf16.f32 "
        "{%0,%1,%2,%3}, {%4,%5,%6,%7}, {%8,%9}, {%0,%1,%2,%3};"
        : "+f"(d[0]), "+f"(d[1]), "+f"(d[2]), "+f"(d[3])
        : "r"(a[0]), "r"(a[1]), "r"(a[2]), "r"(a[3]), "r"(b[0]), "r"(b[1]));
}

// ---------------------------------------------------------------------------
// 1) build_P: P = emb_slice @ W (fp32). grid 192, block 256, 32 rows/blk.
// ---------------------------------------------------------------------------
__global__ void __launch_bounds__(256) build_P(const float* __restrict__ emb,
                                               const float* __restrict__ W) {
    __shared__ float stage[32 * 66];
    int tid = threadIdx.x;
    int r0  = blockIdx.x * 32;
    int b   = r0 / SLEN;
    int u0  = r0 - b * SLEN;

    float acc[32];
    #pragma unroll
    for (int i = 0; i < 32; ++i) acc[i] = 0.f;

    for (int e0 = 0; e0 < EE; e0 += 64) {
        __syncthreads();
        for (int idx = tid; idx < 32 * 64; idx += 256) {
            int i = idx >> 6, e = idx & 63;
            stage[i * 66 + e] = emb[((b * TT) + 64 + u0 + i) * EE + e0 + e];
        }
        __syncthreads();
        #pragma unroll 4
        for (int e = 0; e < 64; ++e) {
            float w = W[(e0 + e) * CC + tid];
            #pragma unroll
            for (int i = 0; i < 32; ++i) acc[i] += stage[i * 66 + e] * w;
        }
    }
    #pragma unroll
    for (int i = 0; i < 32; ++i) g_P[(r0 + i) * CC + tid] = acc[i];
}

// ---------------------------------------------------------------------------
// 2) split_A: A3 row = [hi(P) | hi(P) | lo(P)]; zeroes head/tail.
// ---------------------------------------------------------------------------
__global__ void __launch_bounds__(256) split_A() {
    int r = blockIdx.x, tid = threadIdx.x;
    float x = g_P[r * CC + tid];
    __nv_bfloat16 hi = __float2bfloat16(x);
    __nv_bfloat16 lo = __float2bfloat16(x - __bfloat162float(hi));
    size_t base = (size_t)r * K3;
    g_A3[base + tid]       = hi;
    g_A3[base + 256 + tid] = hi;
    g_A3[base + 512 + tid] = lo;
    if (tid == 0) g_head[r] = 0.f;
    if (tid < 11) g_tail[r * 11 + tid] = 0.f;
}

// ---------------------------------------------------------------------------
// 3) split_B: B3 row = [hi(C) | lo(C) | hi(C)] from gathered ctx.
// ---------------------------------------------------------------------------
__global__ void __launch_bounds__(256) split_B(const float* __restrict__ ctx) {
    int c = blockIdx.x, tid = threadIdx.x;
    int j = c / SLEN, v = c - j * SLEN;
    float x = ctx[((j * TT) + 63 + v) * CC + tid];
    __nv_bfloat16 hi = __float2bfloat16(x);
    __nv_bfloat16 lo = __float2bfloat16(x - __bfloat162float(hi));
    size_t base = (size_t)c * K3;
    g_B3[base + tid]       = hi;
    g_B3[base + 256 + tid] = lo;
    g_B3[base + 512 + tid] = hi;
}

// ---------------------------------------------------------------------------
// 4) positives: g_pos[r][s] = dot(P[r], ctx[b][63+u-s]) fp32. 1 warp/row.
// ---------------------------------------------------------------------------
__global__ void __launch_bounds__(256) positives(const float* __restrict__ ctx) {
    int tid = threadIdx.x, wid = tid >> 5, lane = tid & 31;
    int r = blockIdx.x * 8 + wid;
    int b = r / SLEN, u = r - b * SLEN;

    float p[8];
    #pragma unroll
    for (int i = 0; i < 8; ++i) p[i] = g_P[r * CC + lane + i * 32];

    int smax = (u < 11) ? u : 11;
    for (int s = 0; s <= smax; ++s) {
        const float* crow = ctx + ((b * TT) + 63 + (u - s)) * CC;
        float acc = 0.f;
        #pragma unroll
        for (int i = 0; i < 8; ++i) acc += p[i] * crow[lane + i * 32];
        #pragma unroll
        for (int off = 16; off; off >>= 1)
            acc += __shfl_down_sync(0xffffffffu, acc, off);
        if (lane == 0) g_pos[r * NSTEPS + s] = acc;
    }
}

// ---------------------------------------------------------------------------
// 5) gemm_mma: bf16 mma.sync GEMM with cp.async 2-stage pipeline + ldmatrix.
//    128x128 tile/CTA, 8 warps (2Mx4N), warp = 64x32. grid (48,48), block 256.
//    smem: 2 stages x (sA + sB) x 128 x SST bf16 = 40960 B.
// ---------------------------------------------------------------------------
__global__ void __launch_bounds__(256) gemm_mma() {
    __shared__ __nv_bfloat16 sA[2][128 * SST];
    __shared__ __nv_bfloat16 sB[2][128 * SST];

    int tid  = threadIdx.x;
    int wid  = tid >> 5;
    int lane = tid & 31;
    int g    = lane >> 2;          // 0..7
    int tg   = lane & 3;           // 0..3
    int wM   = wid & 1;
    int wN   = wid >> 1;
    int row0 = blockIdx.y * 128;
    int col0 = blockIdx.x * 128;

    // per-thread load slots: 4 x 16B (A if slot<512 else B)
    int loadIdx[4], loadRR[4], loadCU[4];
    #pragma unroll
    for (int i = 0; i < 4; ++i) {
        int idx = tid + i * 256;              // 0..1023
        loadIdx[i] = idx >> 9;                // 0 = A, 1 = B
        loadRR[i]  = (idx & 511) >> 2;        // row 0..127
        loadCU[i]  = (idx & 3) * 8;           // bf16 offset (16B units)
    }

    auto issue_load = [&](int ch, int st) {
        #pragma unroll
        for (int i = 0; i < 4; ++i) {
            int rr = loadRR[i], cu = loadCU[i];
            if (loadIdx[i] == 0) {
                uint32_t sa = smem_u32(&sA[st][rr * SST + cu]);
                CP_ASYNC16(sa, &g_A3[(size_t)(row0 + rr) * K3 + ch * KCH + cu]);
            } else {
                uint32_t sa = smem_u32(&sB[st][rr * SST + cu]);
                CP_ASYNC16(sa, &g_B3[(size_t)(col0 + rr) * K3 + ch * KCH + cu]);
            }
        }
        CP_COMMIT();
    };

    float d[4][4][4];
    #pragma unroll
    for (int mi = 0; mi < 4; ++mi)
        #pragma unroll
        for (int ni = 0; ni < 4; ++ni)
            #pragma unroll
            for (int q = 0; q < 4; ++q) d[mi][ni][q] = 0.f;

    issue_load(0, 0);

    int lr  = lane & 15;          // fragment row within 16
    int lcb = (lane >> 4) * 8;    // fragment 8-col block

    for (int ch = 0; ch < NCH; ++ch) {
        int st = ch & 1;
        if (ch + 1 < NCH) issue_load(ch + 1, (ch + 1) & 1);
        if (ch + 1 < NCH) { CP_WAIT(1); } else { CP_WAIT(0); }
        __syncthreads();

        #pragma unroll
        for (int ks = 0; ks < KCH / 16; ++ks) {
            int kb = ks * 16;
            uint32_t bfr[2][4];   // [pair][b0_n0, b0_n8, b1_n0, b1_n8]
            #pragma unroll
            for (int pr = 0; pr < 2; ++pr) {
                uint32_t addr = smem_u32(
                    &sB[st][(wN * 32 + pr * 16 + lr) * SST + kb + lcb]);
                LDMX4(bfr[pr][0], bfr[pr][1], bfr[pr][2], bfr[pr][3], addr);
            }
            #pragma unroll
            for (int mi = 0; mi < 4; ++mi) {
                uint32_t afr[4];
                uint32_t addr = smem_u32(
                    &sA[st][(wM * 64 + mi * 16 + lr) * SST + kb + lcb]);
                LDMX4(afr[0], afr[1], afr[2], afr[3], addr);
                #pragma unroll
                for (int pr = 0; pr < 2; ++pr) {
                    uint32_t b0[2] = {bfr[pr][0], bfr[pr][2]};   // n-block pr*2
                    uint32_t b1[2] = {bfr[pr][1], bfr[pr][3]};   // n-block pr*2+1
                    mma16816(d[mi][pr * 2],     afr, b0);
                    mma16816(d[mi][pr * 2 + 1], afr, b1);
                }
            }
        }
        __syncthreads();
    }

    // ---- epilogue: exp + head/tail ----
    float headLo[4] = {0, 0, 0, 0}, headHi[4] = {0, 0, 0, 0};
    #pragma unroll
    for (int mi = 0; mi < 4; ++mi) {
        int rLo = row0 + wM * 64 + mi * 16 + g;
        int rHi = rLo + 8;
        #pragma unroll
        for (int ni = 0; ni < 4; ++ni) {
            int c0c = col0 + wN * 32 + ni * 8 + tg * 2;
            #pragma unroll
            for (int q = 0; q < 2; ++q) {
                int cc = c0c + q;
                int v  = cc % SLEN;
                float eLo = __expf(d[mi][ni][q]     - OFFSET);
                float eHi = __expf(d[mi][ni][q + 2] - OFFSET);
                if (v < 181) { headLo[mi] += eLo; headHi[mi] += eHi; }
                else {
                    atomicAdd(&g_tail[rLo * 11 + (v - 181)], eLo);
                    atomicAdd(&g_tail[rHi * 11 + (v - 181)], eHi);
                }
            }
        }
    }
    #pragma unroll
    for (int mi = 0; mi < 4; ++mi) {
        float lo = headLo[mi], hi = headHi[mi];
        lo += __shfl_down_sync(0xffffffffu, lo, 2, 4);
        lo += __shfl_down_sync(0xffffffffu, lo, 1, 4);
        hi += __shfl_down_sync(0xffffffffu, hi, 2, 4);
        hi += __shfl_down_sync(0xffffffffu, hi, 1, 4);
        if (tg == 0) {
            int rLo = row0 + wM * 64 + mi * 16 + g;
            atomicAdd(&g_head[rLo],     lo);
            atomicAdd(&g_head[rLo + 8], hi);
        }
    }
}

// ---------------------------------------------------------------------------
// 6) finalize: S_s = head + prefix(tails) (addition only). 1024 threads.
// ---------------------------------------------------------------------------
__global__ void __launch_bounds__(1024) finalize(float* __restrict__ out, int out_size) {
    __shared__ double sred[1024];
    __shared__ float slogN[NSTEPS];
    int tid = threadIdx.x;
    if (tid < NSTEPS) slogN[tid] = logf((float)(BATCH * (SLEN - tid)));
    __syncthreads();

    double s = 0.0;
    for (int r = tid; r < NROWS; r += 1024) {
        float hd = g_head[r];
        float pref[12];
        pref[0] = 0.f;
        #pragma unroll
        for (int t = 0; t < 11; ++t) pref[t + 1] = pref[t] + g_tail[r * 11 + t];
        int u = r % SLEN;
        int smax = (u < 11) ? u : 11;
        for (int st = 0; st <= smax; ++st) {
            float S = hd + pref[11 - st];
            float lse = OFFSET + logf(fmaxf(S, 1e-35f)) - slogN[st];
            s += (double)(g_pos[r * NSTEPS + st] - lse);
        }
    }
    sred[tid] = s;
    __syncthreads();
    for (int k = 512; k > 0; k >>= 1) {
        if (tid < k) sred[tid] += sred[tid + k];
        __syncthreads();
    }
    float val = (float)(-sred[0] / TOTAL_COUNT);
    for (int i = tid; i < out_size; i += 1024) out[i] = val;
}

// ---------------------------------------------------------------------------
extern "C" void kernel_launch(void* const* d_in, const int* in_sizes, int n_in,
                              void* d_out, int out_size) {
    int wIdx = -1;
    for (int i = 0; i < n_in; ++i)
        if (in_sizes[i] == EE * CC) { wIdx = i; break; }
    if (wIdx < 0) wIdx = 2;
    int others[2]; int no = 0;
    for (int i = 0; i < n_in && no < 2; ++i)
        if (i != wIdx) others[no++] = i;

    const float* embeddings = (const float*)d_in[others[0]];  // (32,256,256)
    const float* contexts   = (const float*)d_in[others[1]];  // (32,256,256)
    const float* W          = (const float*)d_in[wIdx];       // (256,256)
    float* out = (float*)d_out;

    build_P<<<NROWS / 32, 256>>>(embeddings, W);
    split_A<<<NROWS, 256>>>();
    split_B<<<NROWS, 256>>>(contexts);
    positives<<<NROWS / 8, 256>>>(contexts);
    gemm_mma<<<dim3(48, 48), 256>>>();
    finalize<<<1, 1024>>>(out, out_size);
}